// round 17
// baseline (speedup 1.0000x reference)
#include <cuda_runtime.h>
#include <math.h>

// Problem constants
#define TT 2048
#define BB 4
#define II 1024
#define HH 1024
#define GG (4 * HH)  // 4096 gate rows

// ---------------- scratch (static device globals; no allocations) ----------
__device__ float g_pre[(size_t)TT * BB * GG];  // [8192][4096] x@W_in^T (128 MB)
__device__ float g_h[2][BB * HH];              // double-buffered hidden state
__device__ unsigned g_bar;                     // single barrier counter (proven)

// packed fp32x2 FMA: d.lo += a.lo*b.lo ; d.hi += a.hi*b.hi (sm_100+)
__device__ __forceinline__ void ffma2(unsigned long long& d, unsigned long long a,
                                      unsigned long long b) {
    asm("fma.rn.f32x2 %0, %1, %2, %0;" : "+l"(d) : "l"(a), "l"(b));
}
__device__ __forceinline__ float ull_lo(unsigned long long v) {
    return __uint_as_float((unsigned)v);
}
__device__ __forceinline__ float ull_hi(unsigned long long v) {
    return __uint_as_float((unsigned)(v >> 32));
}
__device__ __forceinline__ unsigned long long dup2(float f) {
    unsigned long long d;
    unsigned u = __float_as_uint(f);
    asm("mov.b64 %0, {%1, %1};" : "=l"(d) : "r"(u));
    return d;
}
__device__ __forceinline__ float tanh_fast(float x) {
    float r;
    asm("tanh.approx.f32 %0, %1;" : "=f"(r) : "f"(x));
    return r;
}
// sigma(x) = 0.5*tanh(x/2) + 0.5  (1 MUFU + 2 FMA vs exp+add+rcp chain)
__device__ __forceinline__ float sig_fast(float x) {
    return fmaf(tanh_fast(0.5f * x), 0.5f, 0.5f);
}

// ---------------- kernel 1: pre = x @ W_in^T  (M=8192, N=4096, K=1024) ------
// Double-buffered fp32x2 GEMM: BM=128, BN=128, BK=16, 256 threads, 8x8
// tile/thread. B staged PRE-DUPLICATED as f32-pair ull (dup movs hoisted out
// of the inner loop). One __syncthreads per k-iter; next tile LDG overlapped
// with compute. 48 KB smem -> 2 CTAs/SM. Block (0,0) resets rec scratch.
#define GBM 128
#define GBN 128
#define GBK 16

__global__ __launch_bounds__(256) void gemm_pre(const float* __restrict__ x,
                                                const float* __restrict__ Win) {
    extern __shared__ __align__(16) float smg[];
    float* As = smg;                                        // [2][16][128] f32 16 KB
    unsigned long long* Bs = (unsigned long long*)(smg + 2 * GBK * GBM);  // [2][16][128] ull 32 KB

    const int tid = threadIdx.x;
    const int tx = tid & 15;        // 0..15  -> N (8 cols each)
    const int ty = tid >> 4;        // 0..15  -> M (8 rows each)
    const int mBase = blockIdx.y * GBM;
    const int nBase = blockIdx.x * GBN;

    // ---- inlined init (one block only): reset barrier + h0 = 0 ----
    if (blockIdx.x == 0 && blockIdx.y == 0) {
        if (tid == 0) g_bar = 0u;
#pragma unroll
        for (int i = 0; i < (2 * BB * HH) / 256; i++)
            ((float*)g_h)[i * 256 + tid] = 0.0f;
    }

    // Per-thread staging coordinates (two float4 each for A and B).
    const int idA0 = tid * 2, idA1 = tid * 2 + 1;
    const int mA0 = idA0 >> 2, kA0 = (idA0 & 3) * 4;
    const int mA1 = idA1 >> 2, kA1 = (idA1 & 3) * 4;

    unsigned long long acc2[4][8];
#pragma unroll
    for (int i = 0; i < 4; i++)
#pragma unroll
        for (int j = 0; j < 8; j++) acc2[i][j] = 0ull;

    // Stage tile 0 into buffer 0.
    {
        float4 a0 = *(const float4*)&x[(size_t)(mBase + mA0) * II + kA0];
        float4 a1 = *(const float4*)&x[(size_t)(mBase + mA1) * II + kA1];
        float4 b0 = *(const float4*)&Win[(size_t)(nBase + mA0) * II + kA0];
        float4 b1 = *(const float4*)&Win[(size_t)(nBase + mA1) * II + kA1];
        As[(kA0 + 0) * GBM + mA0] = a0.x; As[(kA0 + 1) * GBM + mA0] = a0.y;
        As[(kA0 + 2) * GBM + mA0] = a0.z; As[(kA0 + 3) * GBM + mA0] = a0.w;
        As[(kA1 + 0) * GBM + mA1] = a1.x; As[(kA1 + 1) * GBM + mA1] = a1.y;
        As[(kA1 + 2) * GBM + mA1] = a1.z; As[(kA1 + 3) * GBM + mA1] = a1.w;
        Bs[(kA0 + 0) * GBN + mA0] = dup2(b0.x); Bs[(kA0 + 1) * GBN + mA0] = dup2(b0.y);
        Bs[(kA0 + 2) * GBN + mA0] = dup2(b0.z); Bs[(kA0 + 3) * GBN + mA0] = dup2(b0.w);
        Bs[(kA1 + 0) * GBN + mA1] = dup2(b1.x); Bs[(kA1 + 1) * GBN + mA1] = dup2(b1.y);
        Bs[(kA1 + 2) * GBN + mA1] = dup2(b1.z); Bs[(kA1 + 3) * GBN + mA1] = dup2(b1.w);
    }
    __syncthreads();

    const int NIT = II / GBK;  // 64
    for (int k0 = 0; k0 < NIT; k0++) {
        const int cur = k0 & 1;
        float4 a0, a1, b0, b1;
        const bool pf = (k0 + 1 < NIT);
        if (pf) {
            const int kb = (k0 + 1) * GBK;
            a0 = *(const float4*)&x[(size_t)(mBase + mA0) * II + kb + kA0];
            a1 = *(const float4*)&x[(size_t)(mBase + mA1) * II + kb + kA1];
            b0 = *(const float4*)&Win[(size_t)(nBase + mA0) * II + kb + kA0];
            b1 = *(const float4*)&Win[(size_t)(nBase + mA1) * II + kb + kA1];
        }

        const float* Ac = As + cur * (GBK * GBM);
        const unsigned long long* Bc = Bs + cur * (GBK * GBN);
#pragma unroll
        for (int kk = 0; kk < GBK; kk++) {
            ulonglong2 t0 = *(const ulonglong2*)&Ac[kk * GBM + ty * 8];
            ulonglong2 t1 = *(const ulonglong2*)&Ac[kk * GBM + ty * 8 + 4];
            unsigned long long a2[4] = {t0.x, t0.y, t1.x, t1.y};
            ulonglong2 bquad0 = *(const ulonglong2*)&Bc[kk * GBN + tx * 8];
            ulonglong2 bquad1 = *(const ulonglong2*)&Bc[kk * GBN + tx * 8 + 2];
            ulonglong2 bquad2 = *(const ulonglong2*)&Bc[kk * GBN + tx * 8 + 4];
            ulonglong2 bquad3 = *(const ulonglong2*)&Bc[kk * GBN + tx * 8 + 6];
            unsigned long long bd[8] = {bquad0.x, bquad0.y, bquad1.x, bquad1.y,
                                        bquad2.x, bquad2.y, bquad3.x, bquad3.y};
#pragma unroll
            for (int i = 0; i < 4; i++)
#pragma unroll
                for (int j = 0; j < 8; j++) ffma2(acc2[i][j], a2[i], bd[j]);
        }

        if (pf) {
            float* An = As + (cur ^ 1) * (GBK * GBM);
            unsigned long long* Bn = Bs + (cur ^ 1) * (GBK * GBN);
            An[(kA0 + 0) * GBM + mA0] = a0.x; An[(kA0 + 1) * GBM + mA0] = a0.y;
            An[(kA0 + 2) * GBM + mA0] = a0.z; An[(kA0 + 3) * GBM + mA0] = a0.w;
            An[(kA1 + 0) * GBM + mA1] = a1.x; An[(kA1 + 1) * GBM + mA1] = a1.y;
            An[(kA1 + 2) * GBM + mA1] = a1.z; An[(kA1 + 3) * GBM + mA1] = a1.w;
            Bn[(kA0 + 0) * GBN + mA0] = dup2(b0.x); Bn[(kA0 + 1) * GBN + mA0] = dup2(b0.y);
            Bn[(kA0 + 2) * GBN + mA0] = dup2(b0.z); Bn[(kA0 + 3) * GBN + mA0] = dup2(b0.w);
            Bn[(kA1 + 0) * GBN + mA1] = dup2(b1.x); Bn[(kA1 + 1) * GBN + mA1] = dup2(b1.y);
            Bn[(kA1 + 2) * GBN + mA1] = dup2(b1.z); Bn[(kA1 + 3) * GBN + mA1] = dup2(b1.w);
        }
        __syncthreads();
    }

#pragma unroll
    for (int i = 0; i < 4; i++) {
#pragma unroll
        for (int half = 0; half < 2; half++) {
            float4 vlo = make_float4(ull_lo(acc2[i][half * 4 + 0]), ull_lo(acc2[i][half * 4 + 1]),
                                     ull_lo(acc2[i][half * 4 + 2]), ull_lo(acc2[i][half * 4 + 3]));
            float4 vhi = make_float4(ull_hi(acc2[i][half * 4 + 0]), ull_hi(acc2[i][half * 4 + 1]),
                                     ull_hi(acc2[i][half * 4 + 2]), ull_hi(acc2[i][half * 4 + 3]));
            *(float4*)&g_pre[(size_t)(mBase + ty * 8 + 2 * i + 0) * GG + nBase + tx * 8 + half * 4] = vlo;
            *(float4*)&g_pre[(size_t)(mBase + ty * 8 + 2 * i + 1) * GG + nBase + tx * 8 + half * 4] = vhi;
        }
    }
}

// ---------------- kernel 2: persistent recurrence (FROZEN from R15) ---------
// 128 CTAs x 512 threads (16 warps; 1 CTA/SM via 130 KB smem). CTA owns 8
// hidden units (32 gate rows, 128 KB smem). Warp w: gate = w>>2, K-quarter
// = w&3; 8 rows x 4 batches over K=256, packed FFMA2, h loaded L2->registers,
// 5-stage shfl transpose-reduce. Split-barrier tail (R15-proven).
#define NBLK 128
#define UPB 8
#define ROWS 32
#define RTH 512

__global__ __launch_bounds__(RTH) void lstm_rec(const float* __restrict__ Whh,
                                                float* __restrict__ out) {
    extern __shared__ float sm[];
    float* W_s = sm;                          // [32][1024] 128 KB
    float* part_s = W_s + ROWS * HH;          // [4 quarter][4 gate][32]  2 KB
    volatile unsigned* sflag = (volatile unsigned*)(part_s + 4 * 4 * 32);

    const int tid = threadIdx.x;
    const int blk = blockIdx.x;
    const int warp = tid >> 5;
    const int lane = tid & 31;
    const int gate = warp >> 2;               // 0..3
    const int q = warp & 3;                   // K-quarter 0..3

    // Stage W: local row r = gate*8 + u  <-  Whh[gate*1024 + blk*8 + u]
    for (int id = tid; id < ROWS * (HH / 4); id += RTH) {
        int r = id / (HH / 4);
        int c4 = id % (HH / 4);
        int g = r >> 3, ul = r & 7;
        ((float4*)&W_s[r * HH])[c4] =
            ((const float4*)&Whh[(size_t)(g * HH + blk * UPB + ul) * HH])[c4];
    }
    if (tid == 0) *sflag = 0u;
    __syncthreads();

    // warp0 persistent cell state: lane = u*4 + b
    const int u = lane >> 2, b = lane & 3;
    const int ug = blk * UPB + u;
    float c_val = 0.0f;

    const float* Wbase = &W_s[gate * UPB * HH + q * (HH / 4)];
    const int hoff = q * (HH / 4) + lane * 4;  // this lane's K slice base

    for (int t = 0; t < TT; t++) {
        // Prefetch this step's pre-activations (consumed ~1500 cyc later).
        float pre_r[4];
        if (warp == 0) {
#pragma unroll
            for (int g = 0; g < 4; g++)
                pre_r[g] = __ldcs(&g_pre[(size_t)(t * BB + b) * GG + g * HH + ug]);
        }

        // h: L2 -> registers, lane-private slices (issue all 8 LDG.128 up
        // front; latency overlapped by the 16-warp mix and the W LDS stream).
        const float* hg = g_h[t & 1];
        ulonglong2 hv[2][4];
#pragma unroll
        for (int it = 0; it < 2; it++)
#pragma unroll
            for (int bb = 0; bb < 4; bb++)
                hv[it][bb] = __ldcg((const ulonglong2*)&hg[bb * HH + hoff + it * 128]);

        // GEMV: 8 rows x 4 batches over K=256 (2 iterations of 128).
        unsigned long long acc[8][4];
#pragma unroll
        for (int j = 0; j < 8; j++)
#pragma unroll
            for (int bb = 0; bb < 4; bb++) acc[j][bb] = 0ull;

#pragma unroll
        for (int it = 0; it < 2; it++) {
            const int base = it * 128 + lane * 4;
#pragma unroll
            for (int j = 0; j < 8; j++) {
                ulonglong2 wv = *(const ulonglong2*)&Wbase[j * HH + base];
#pragma unroll
                for (int bb = 0; bb < 4; bb++) {
                    ffma2(acc[j][bb], wv.x, hv[it][bb].x);
                    ffma2(acc[j][bb], wv.y, hv[it][bb].y);
                }
            }
        }

        // Collapse packed accumulators -> 32 scalars (index = j*4 + bb = u*4+b)
        float a[32];
#pragma unroll
        for (int j = 0; j < 8; j++)
#pragma unroll
            for (int bb = 0; bb < 4; bb++)
                a[j * 4 + bb] = ull_lo(acc[j][bb]) + ull_hi(acc[j][bb]);

        // Register transpose-reduce: lane l ends with full sum of index l.
#pragma unroll
        for (int s = 16; s >= 1; s >>= 1) {
            const bool up = (lane & s) != 0;
#pragma unroll
            for (int k = 0; k < s; k++) {
                float sendv = up ? a[k] : a[k + s];
                float keepv = up ? a[k + s] : a[k];
                float got = __shfl_xor_sync(0xFFFFFFFFu, sendv, s);
                a[k] = keepv + got;
            }
        }
        part_s[(q * 4 + gate) * 32 + lane] = a[0];

        if (warp == 0) {
            // Wait for all producers' part_s (480 arrivals + 32 sync = 512).
            asm volatile("bar.sync 1, %0;" ::"r"(RTH) : "memory");

            // Cell update: lane = u*4 + b. Sum the 4 K-quarter partials.
            float gsum[4];
#pragma unroll
            for (int g = 0; g < 4; g++) {
                gsum[g] = pre_r[g];
#pragma unroll
                for (int qq = 0; qq < 4; qq++)
                    gsum[g] += part_s[(qq * 4 + g) * 32 + lane];
            }
            float i_s = sig_fast(gsum[0]);
            float f_s = sig_fast(gsum[1]);
            float g_t = tanh_fast(gsum[2]);
            float o_s = sig_fast(gsum[3]);
            c_val = f_s * c_val + i_s * g_t;
            float h = o_s * tanh_fast(c_val);
            g_h[(t + 1) & 1][b * HH + ug] = h;                      // next step input
            out[(size_t)(t * BB + b) * HH + ug] = h;                // layer output
            if (t == TT - 1) {
                out[(size_t)TT * BB * HH + b * HH + ug] = h;            // h_T
                out[(size_t)TT * BB * HH + BB * HH + b * HH + ug] = c_val;  // c_T
            }
            __syncwarp();
            if (lane == 0) {
                __threadfence();  // cumulative: orders warp-0's h stores (via syncwarp)
                atomicAdd(&g_bar, 1u);
                const unsigned target = (unsigned)(t + 1) * NBLK;
                while (*((volatile unsigned*)&g_bar) < target) {
                }
            }
            __syncwarp();         // all warp-0 lanes wait for the poll
            if (lane == 0) *sflag = (unsigned)(t + 1);  // release the CTA
        } else {
            // Producer: signal part_s written, then spin on the smem flag
            // until warp 0 certifies h_{t+1} is globally visible.
            asm volatile("bar.arrive 1, %0;" ::"r"(RTH) : "memory");
            const unsigned tgt = (unsigned)(t + 1);
            while (*sflag < tgt) {
            }
        }
    }
}

// ---------------- launch ----------------------------------------------------
extern "C" void kernel_launch(void* const* d_in, const int* in_sizes, int n_in,
                              void* d_out, int out_size) {
    const float* x   = (const float*)d_in[0];   // [T,B,I]
    const float* Win = (const float*)d_in[1];   // [4H,I]
    const float* Whh = (const float*)d_in[2];   // [4H,H]
    float* out = (float*)d_out;

    const int gemm_smem = 2 * GBK * GBM * (int)sizeof(float) +
                          2 * GBK * GBN * (int)sizeof(unsigned long long);  // 48 KB
    cudaFuncSetAttribute(gemm_pre, cudaFuncAttributeMaxDynamicSharedMemorySize, gemm_smem);

    const int rec_smem = (ROWS * HH + 4 * 4 * 32 + 8) * (int)sizeof(float);
    cudaFuncSetAttribute(lstm_rec, cudaFuncAttributeMaxDynamicSharedMemorySize, rec_smem);

    gemm_pre<<<dim3(GG / GBN, (TT * BB) / GBM), 256, gemm_smem>>>(x, Win);
    lstm_rec<<<NBLK, RTH, rec_smem>>>(Whh, out);
}